// round 10
// baseline (speedup 1.0000x reference)
#include <cuda_runtime.h>
#include <stdint.h>

// adjacency_full[i, neighbor_indices[i, j]] = adjacency_values[i, j]
// N = 8192, K = 64. Output: N*N fp32 (256 MB).
//
// Persistent double-buffered TMA producer. Each CTA owns two 32KB smem row
// buffers (dynamic smem, 64KB) and processes 8 rows (grid-stride 1024).
// Buffers are zeroed ONCE; per row we only:
//   wait_group 1  (buffer from 2 rows ago is drained)
//   re-zero that buffer's previous 64 scatter positions (~256B STS)
//   scatter the new 64 (col,val) pairs
//   fence.proxy.async + cp.async.bulk 32KB smem->gmem (fire and forget)
// The TMA engine streams rows continuously while the CTA builds the next one.

#define N_PATCHES 8192
#define K_NEIGH   64
#define THREADS   256
#define GRID      1024
#define ROW_BYTES (N_PATCHES * 4)        // 32 KB per row
#define SMEM_BYTES (2 * ROW_BYTES)       // 64 KB double buffer

__global__ void __launch_bounds__(THREADS)
tma_pipe_kernel(const float* __restrict__ vals,
                const int*   __restrict__ idx,
                float* __restrict__ out)
{
    extern __shared__ __align__(128) float sbuf[];   // [2][N_PATCHES]
    const int tid = threadIdx.x;

    // Zero both buffers once (vectorized STS).
    {
        float4* s4 = reinterpret_cast<float4*>(sbuf);
        const float4 z4 = make_float4(0.f, 0.f, 0.f, 0.f);
        #pragma unroll
        for (int j = 0; j < (2 * N_PATCHES / 4) / THREADS; j++)
            s4[tid + j * THREADS] = z4;
    }

    // Per-thread previous scatter column for each buffer (col 0 is a safe
    // dummy: clearing an untouched position writes 0 over 0).
    int prev0 = 0, prev1 = 0;

    // Prefetch first row's operands.
    int   c = 0;
    float v = 0.f;
    {
        int r0 = blockIdx.x;
        if (tid < K_NEIGH) {
            int t = r0 * K_NEIGH + tid;
            c = idx[t];
            v = vals[t];
        }
    }

    __syncthreads();   // buffers zeroed before first scatter

    int it = 0;
    for (int r = blockIdx.x; r < N_PATCHES; r += GRID, ++it) {
        const int b = it & 1;
        float* row = sbuf + b * N_PATCHES;

        // Prefetch next row's operands (latency hidden under this row's work).
        int   cn = 0;
        float vn = 0.f;
        const int rn = r + GRID;
        if (tid < K_NEIGH && rn < N_PATCHES) {
            int t = rn * K_NEIGH + tid;
            cn = idx[t];
            vn = vals[t];
        }

        // Ensure the TMA store that read this buffer (issued 2 rows ago) is
        // done before we mutate it. Only thread 0 committed groups.
        if (it >= 2 && tid == 0)
            asm volatile("cp.async.bulk.wait_group 1;" ::: "memory");
        __syncthreads();

        // Clear the previous scatter positions in this buffer.
        if (tid < K_NEIGH)
            row[b ? prev1 : prev0] = 0.f;
        __syncthreads();   // clears happen-before new writes (col collisions)

        // Scatter the new 64 values.
        if (tid < K_NEIGH) {
            row[c] = v;
            if (b) prev1 = c; else prev0 = c;
        }
        __syncthreads();   // all STS visible before the TMA issue

        // Issue the 32KB bulk store (async proxy streams it out).
        if (tid == 0) {
            asm volatile("fence.proxy.async.shared::cta;" ::: "memory");
            uint32_t saddr;
            asm("{ .reg .u64 t; cvta.to.shared.u64 t, %1; cvt.u32.u64 %0, t; }"
                : "=r"(saddr) : "l"(row));
            float* dst = out + (size_t)r * N_PATCHES;
            asm volatile(
                "cp.async.bulk.global.shared::cta.bulk_group [%0], [%1], %2;"
                :: "l"(dst), "r"(saddr), "n"(ROW_BYTES) : "memory");
            asm volatile("cp.async.bulk.commit_group;" ::: "memory");
        }

        c = cn;
        v = vn;
    }

    // Keep smem alive until all outstanding bulk stores have drained.
    if (tid == 0)
        asm volatile("cp.async.bulk.wait_group 0;" ::: "memory");
}

extern "C" void kernel_launch(void* const* d_in, const int* in_sizes, int n_in,
                              void* d_out, int out_size)
{
    const float* vals = (const float*)d_in[0];   // [N, K] float32
    const int*   idx  = (const int*)  d_in[1];   // [N, K] int32
    float* out = (float*)d_out;                  // [N, N] float32

    static int smem_set = 0;
    if (!smem_set) {
        cudaFuncSetAttribute(tma_pipe_kernel,
                             cudaFuncAttributeMaxDynamicSharedMemorySize,
                             SMEM_BYTES);
        smem_set = 1;
    }
    tma_pipe_kernel<<<GRID, THREADS, SMEM_BYTES, 0>>>(vals, idx, out);
}

// round 11
// speedup vs baseline: 1.0100x; 1.0100x over previous
#include <cuda_runtime.h>
#include <stdint.h>

// adjacency_full[i, neighbor_indices[i, j]] = adjacency_values[i, j]
// N = 8192, K = 64. Output: N*N fp32 (256 MB).
//
// Immutable-zero-buffer TMA streamer. Each CTA zeroes ONE 32KB smem buffer
// once, then for each of its 8 rows:
//   - issues cp.async.bulk (32KB zeros, smem -> row)    [async proxy]
//   - two rows later (wait_group 2 => that store done) scatters the row's
//     64 values with plain STGs into the freshly-zeroed, L2-dirty lines.
// The zero buffer is never mutated, so no double buffering, no per-row smem
// rebuild, no per-row re-zero. SM work per row: 1 TMA issue + 64 STGs.

#define N_PATCHES 8192
#define K_NEIGH   64
#define THREADS   128
#define GRID      1024                    // 8 rows per CTA, exact
#define ROWS_PER  (N_PATCHES / GRID)      // 8
#define ROW_BYTES (N_PATCHES * 4)         // 32 KB

__global__ void __launch_bounds__(THREADS)
tma_zero_stream_kernel(const float* __restrict__ vals,
                       const int*   __restrict__ idx,
                       float* __restrict__ out)
{
    __shared__ __align__(128) float zbuf[N_PATCHES];   // 32 KB, zeros forever
    const int tid = threadIdx.x;

    // Preload all 8 rows' scatter operands (hidden under the smem zeroing).
    int   c[ROWS_PER];
    float v[ROWS_PER];
    if (tid < K_NEIGH) {
        #pragma unroll
        for (int i = 0; i < ROWS_PER; i++) {
            int t = (blockIdx.x + i * GRID) * K_NEIGH + tid;
            c[i] = idx[t];
            v[i] = vals[t];
        }
    }

    // Zero the buffer once (vectorized STS: 16 float4 per thread).
    {
        float4* z4p = reinterpret_cast<float4*>(zbuf);
        const float4 z4 = make_float4(0.f, 0.f, 0.f, 0.f);
        #pragma unroll
        for (int j = 0; j < (N_PATCHES / 4) / THREADS; j++)
            z4p[tid + j * THREADS] = z4;
    }
    __syncthreads();
    // Make the generic-proxy STS visible to the async proxy (once).
    asm volatile("fence.proxy.async.shared::cta;" ::: "memory");

    uint32_t saddr;
    asm("{ .reg .u64 t; cvta.to.shared.u64 t, %1; cvt.u32.u64 %0, t; }"
        : "=r"(saddr) : "l"(zbuf));

    // Pipelined: issue store for row i; scatter row i-2 once its store is done.
    #pragma unroll
    for (int i = 0; i < ROWS_PER; i++) {
        const int r = blockIdx.x + i * GRID;
        if (tid == 0) {
            float* dst = out + (size_t)r * N_PATCHES;
            asm volatile(
                "cp.async.bulk.global.shared::cta.bulk_group [%0], [%1], %2;"
                :: "l"(dst), "r"(saddr), "n"(ROW_BYTES) : "memory");
            asm volatile("cp.async.bulk.commit_group;" ::: "memory");
        }
        if (i >= 2) {
            // stores 0..i-2 are complete once <=2 groups remain outstanding.
            if (tid == 0)
                asm volatile("cp.async.bulk.wait_group 2;" ::: "memory");
            __syncthreads();
            const int rp = blockIdx.x + (i - 2) * GRID;
            if (tid < K_NEIGH)
                out[(size_t)rp * N_PATCHES + c[i - 2]] = v[i - 2];
        }
    }

    // Tail: drain the last two rows.
    if (tid == 0)
        asm volatile("cp.async.bulk.wait_group 1;" ::: "memory");
    __syncthreads();
    if (tid < K_NEIGH)
        out[(size_t)(blockIdx.x + (ROWS_PER - 2) * GRID) * N_PATCHES
            + c[ROWS_PER - 2]] = v[ROWS_PER - 2];

    if (tid == 0)
        asm volatile("cp.async.bulk.wait_group 0;" ::: "memory");
    __syncthreads();
    if (tid < K_NEIGH)
        out[(size_t)(blockIdx.x + (ROWS_PER - 1) * GRID) * N_PATCHES
            + c[ROWS_PER - 1]] = v[ROWS_PER - 1];
}

extern "C" void kernel_launch(void* const* d_in, const int* in_sizes, int n_in,
                              void* d_out, int out_size)
{
    const float* vals = (const float*)d_in[0];   // [N, K] float32
    const int*   idx  = (const int*)  d_in[1];   // [N, K] int32
    float* out = (float*)d_out;                  // [N, N] float32

    tma_zero_stream_kernel<<<GRID, THREADS, 0, 0>>>(vals, idx, out);
}

// round 12
// speedup vs baseline: 1.1155x; 1.1045x over previous
#include <cuda_runtime.h>
#include <stdint.h>

// adjacency_full[i, neighbor_indices[i, j]] = adjacency_values[i, j]
// N = 8192, K = 64. Output: N*N fp32 (256 MB).
//
// Half-row TMA streamer: 2 CTAs per row (16KB tile each), grid = 16384.
// Smaller smem footprint -> ~13 CTAs/SM -> ~2x the outstanding TMA stores
// per SM vs the 32KB one-CTA-per-row variant, keeping the write-drain path
// continuously fed. Per CTA:
//   0) prefetch the row's 64 (col,val); keep the ones in this half
//   1) zero the 16KB smem tile (STS.128)
//   2) predicated scatter of in-range entries into smem
//   3) fence.proxy.async + one 16KB cp.async.bulk to the half-row

#define N_PATCHES 8192
#define K_NEIGH   64
#define TILE      4096                    // columns per CTA (half row)
#define TILE_BYTES (TILE * 4)             // 16 KB
#define THREADS   128
#define TILE_V4   (TILE / 4)              // 1024 float4
#define PER_THR   (TILE_V4 / THREADS)     // 8 float4 per thread

__global__ void __launch_bounds__(THREADS)
tma_half_row_kernel(const float* __restrict__ vals,
                    const int*   __restrict__ idx,
                    float* __restrict__ out)
{
    __shared__ __align__(128) float tile[TILE];   // 16 KB
    const int tid  = threadIdx.x;
    const int r    = blockIdx.x >> 1;             // row
    const int half = blockIdx.x & 1;              // 0: cols [0,4096), 1: [4096,8192)
    const int lo   = half * TILE;

    // Phase 0: prefetch scatter operand (one entry per thread, tid<64).
    int   c = -1;
    float v = 0.f;
    if (tid < K_NEIGH) {
        int t = r * K_NEIGH + tid;
        c = idx[t] - lo;                 // local column, may be out of range
        v = vals[t];
    }

    // Phase 1: zero the tile (8 STS.128 per thread).
    float4* t4 = reinterpret_cast<float4*>(tile);
    const float4 z4 = make_float4(0.f, 0.f, 0.f, 0.f);
    #pragma unroll
    for (int j = 0; j < PER_THR; j++)
        t4[tid + j * THREADS] = z4;
    __syncthreads();

    // Phase 2: predicated scatter (no loops, no divergent search).
    if (tid < K_NEIGH && (unsigned)c < (unsigned)TILE)
        tile[c] = v;
    __syncthreads();

    // Phase 3: one 16KB bulk store smem -> gmem.
    asm volatile("fence.proxy.async.shared::cta;" ::: "memory");
    if (tid == 0) {
        uint32_t saddr;
        asm("{ .reg .u64 t; cvta.to.shared.u64 t, %1; cvt.u32.u64 %0, t; }"
            : "=r"(saddr) : "l"(tile));
        float* dst = out + (size_t)r * N_PATCHES + lo;
        asm volatile(
            "cp.async.bulk.global.shared::cta.bulk_group [%0], [%1], %2;"
            :: "l"(dst), "r"(saddr), "n"(TILE_BYTES) : "memory");
        asm volatile("cp.async.bulk.commit_group;" ::: "memory");
        // smem must stay alive until the bulk store has consumed it.
        asm volatile("cp.async.bulk.wait_group 0;" ::: "memory");
    }
}

extern "C" void kernel_launch(void* const* d_in, const int* in_sizes, int n_in,
                              void* d_out, int out_size)
{
    const float* vals = (const float*)d_in[0];   // [N, K] float32
    const int*   idx  = (const int*)  d_in[1];   // [N, K] int32
    float* out = (float*)d_out;                  // [N, N] float32

    tma_half_row_kernel<<<2 * N_PATCHES, THREADS, 0, 0>>>(vals, idx, out);
}